// round 1
// baseline (speedup 1.0000x reference)
#include <cuda_runtime.h>
#include <math.h>

// Problem constants
//  x: [B=2, T=64, C=16, H=128, W=128] f32
//  qkv convs 3x3 pad1 (16->16), attention heads nh=8, hc=2, D=2*128*128=32768
//  causal softmax over T=64, then out conv 3x3 (16->16)
#define HW 16384

// ---------------- scratch (device globals; no allocations) ----------------
__device__ float g_q[2*64*16*16384];   // q, later reused as attention output y
__device__ float g_k[2*64*16*16384];
__device__ float g_v[2*64*16*16384];
__device__ float g_part[64*16*64*64];  // QK^T partials per k-split
__device__ float g_att[16*64*64];      // softmax probs, stored [bh][s][t]

// ---------------- fused 3x3 conv (NCONV=3: qkv, NCONV=1: output) ----------
// Block: 256 threads, spatial tile 32(w) x 8(h), all NCONV*16 output channels.
// Thread = 4 consecutive pixels (along w) x (NCONV*16/4) channels.
template<int NCONV>
__global__ void __launch_bounds__(256) conv3x3_kernel(
    const float* __restrict__ xin,
    const float* __restrict__ w0, const float* __restrict__ b0,
    const float* __restrict__ w1, const float* __restrict__ b1,
    const float* __restrict__ w2, const float* __restrict__ b2,
    float* __restrict__ out_final)
{
    constexpr int NCH = NCONV * 16;
    constexpr int CPG = NCH / 4;          // channels per channel-group
    extern __shared__ float smem[];
    float* s_in = smem;                   // 16 * 10 * 35 = 5600 floats (halo tile)
    float* s_w  = smem + 16*10*35;        // NCH * 16 * 12 (9 weights padded to 12)
    float* s_b  = s_w + NCH*16*12;        // NCH

    const int tid = threadIdx.x;
    const int bt  = blockIdx.y;                 // image index 0..127
    const int th0 = (blockIdx.x >> 2) * 8;      // tile origin h
    const int tw0 = (blockIdx.x & 3) * 32;      // tile origin w

    const float* x = (NCONV == 3) ? xin : g_q;  // final conv reads y (aliased on g_q)

    // stage weights (padded to 12 floats per (ch, ic) for aligned float4 reads)
    {
        const float* wsrc[3] = {w0, w1, w2};
        for (int idx = tid; idx < NCH*144; idx += 256) {
            int conv = idx / 2304;
            int rem  = idx - conv*2304;     // oc*144 + ic*9 + j
            int oc   = rem / 144;
            int r2   = rem - oc*144;
            int ic   = r2 / 9;
            int j    = r2 - ic*9;
            s_w[((conv*16 + oc)*16 + ic)*12 + j] = wsrc[conv][rem];
        }
        for (int idx = tid; idx < NCH; idx += 256) {
            float bv;
            if (NCONV == 3) bv = (idx < 16) ? b0[idx] : (idx < 32 ? b1[idx-16] : b2[idx-32]);
            else            bv = b0[idx];
            s_b[idx] = bv;
        }
    }

    // stage input tile with halo: rows th0-1..th0+8, cols tw0-1..tw0+32 (zero pad)
    for (int idx = tid; idx < 16*10*34; idx += 256) {
        int c   = idx / 340;
        int rem = idx - c*340;
        int yy  = rem / 34;
        int xx  = rem - yy*34;
        int gh  = th0 + yy - 1;
        int gw  = tw0 + xx - 1;
        float v = 0.f;
        if (gh >= 0 && gh < 128 && gw >= 0 && gw < 128)
            v = x[((size_t)bt*16 + c)*HW + gh*128 + gw];
        s_in[c*350 + yy*35 + xx] = v;   // row stride 35 to stagger banks
    }
    __syncthreads();

    const int pg = tid & 63;          // pixel group 0..63
    const int cg = tid >> 6;          // channel group 0..3
    const int py = pg >> 3;           // tile row 0..7
    const int x0 = (pg & 7) * 4;      // tile col start

    float acc[CPG][4];
#pragma unroll
    for (int c = 0; c < CPG; ++c) {
        float bb = s_b[cg*CPG + c];
#pragma unroll
        for (int p = 0; p < 4; ++p) acc[c][p] = bb;
    }

    for (int ic = 0; ic < 16; ++ic) {
        const float* base = s_in + ic*350 + py*35 + x0;   // patch rows py..py+2
        float p[3][6];
#pragma unroll
        for (int ky = 0; ky < 3; ++ky)
#pragma unroll
            for (int kx = 0; kx < 6; ++kx)
                p[ky][kx] = base[ky*35 + kx];
#pragma unroll
        for (int c = 0; c < CPG; ++c) {
            const float* wp = s_w + ((cg*CPG + c)*16 + ic)*12;
            float4 wA = *(const float4*)wp;
            float4 wB = *(const float4*)(wp + 4);
            float  w8 = wp[8];
#pragma unroll
            for (int px = 0; px < 4; ++px) {
                float s = acc[c][px];
                s = fmaf(p[0][px+0], wA.x, s);
                s = fmaf(p[0][px+1], wA.y, s);
                s = fmaf(p[0][px+2], wA.z, s);
                s = fmaf(p[1][px+0], wA.w, s);
                s = fmaf(p[1][px+1], wB.x, s);
                s = fmaf(p[1][px+2], wB.y, s);
                s = fmaf(p[2][px+0], wB.z, s);
                s = fmaf(p[2][px+1], wB.w, s);
                s = fmaf(p[2][px+2], w8, s);
                acc[c][px] = s;
            }
        }
    }

    const int oh = th0 + py;
    const int ow = tw0 + x0;
#pragma unroll
    for (int c = 0; c < CPG; ++c) {
        int ch   = cg*CPG + c;
        int conv = ch >> 4;
        int oc   = ch & 15;
        size_t off = ((size_t)bt*16 + oc)*HW + oh*128 + ow;
        float4 val = make_float4(acc[c][0], acc[c][1], acc[c][2], acc[c][3]);
        float* outp;
        if (NCONV == 3) outp = (conv == 0) ? g_q : (conv == 1 ? g_k : g_v);
        else            outp = out_final;
        *(float4*)(outp + off) = val;
    }
}

// ---------------- QK^T with K-split ----------------
// grid (64 splits, 16 bh), block 256 = 16x16, each thread a 4x4 att tile.
// D-chunk per block = 512, staged transposed in smem for LDS.128 fragments.
__global__ void __launch_bounds__(256) qk_kernel()
{
    __shared__ float Qs[64][68];   // [kk][t]
    __shared__ float Ks[64][68];   // [kk][s]
    const int bh = blockIdx.y;
    const int b  = bh >> 3, h = bh & 7;
    const int split = blockIdx.x;
    const int tid = threadIdx.x;
    const int ty = tid >> 4, tx = tid & 15;

    float acc[4][4];
#pragma unroll
    for (int i = 0; i < 4; ++i)
#pragma unroll
        for (int j = 0; j < 4; ++j) acc[i][j] = 0.f;

    for (int sub = 0; sub < 8; ++sub) {
        const int kc = split*512 + sub*64;
        __syncthreads();
        for (int i = tid; i < 1024; i += 256) {
            int t  = i >> 4;
            int kq = (i & 15) << 2;
            size_t base = ((size_t)((b*64 + t)*16 + h*2))*HW + kc + kq;
            float4 qa = *(const float4*)(g_q + base);
            float4 ka = *(const float4*)(g_k + base);
            Qs[kq+0][t] = qa.x; Qs[kq+1][t] = qa.y; Qs[kq+2][t] = qa.z; Qs[kq+3][t] = qa.w;
            Ks[kq+0][t] = ka.x; Ks[kq+1][t] = ka.y; Ks[kq+2][t] = ka.z; Ks[kq+3][t] = ka.w;
        }
        __syncthreads();
#pragma unroll 8
        for (int kk = 0; kk < 64; ++kk) {
            float4 a  = *(const float4*)&Qs[kk][ty*4];
            float4 bb = *(const float4*)&Ks[kk][tx*4];
            acc[0][0] = fmaf(a.x, bb.x, acc[0][0]);
            acc[0][1] = fmaf(a.x, bb.y, acc[0][1]);
            acc[0][2] = fmaf(a.x, bb.z, acc[0][2]);
            acc[0][3] = fmaf(a.x, bb.w, acc[0][3]);
            acc[1][0] = fmaf(a.y, bb.x, acc[1][0]);
            acc[1][1] = fmaf(a.y, bb.y, acc[1][1]);
            acc[1][2] = fmaf(a.y, bb.z, acc[1][2]);
            acc[1][3] = fmaf(a.y, bb.w, acc[1][3]);
            acc[2][0] = fmaf(a.z, bb.x, acc[2][0]);
            acc[2][1] = fmaf(a.z, bb.y, acc[2][1]);
            acc[2][2] = fmaf(a.z, bb.z, acc[2][2]);
            acc[2][3] = fmaf(a.z, bb.w, acc[2][3]);
            acc[3][0] = fmaf(a.w, bb.x, acc[3][0]);
            acc[3][1] = fmaf(a.w, bb.y, acc[3][1]);
            acc[3][2] = fmaf(a.w, bb.z, acc[3][2]);
            acc[3][3] = fmaf(a.w, bb.w, acc[3][3]);
        }
    }

    float* dst = g_part + ((size_t)(split*16 + bh))*4096;
#pragma unroll
    for (int i = 0; i < 4; ++i)
        *(float4*)(dst + (ty*4 + i)*64 + tx*4) =
            make_float4(acc[i][0], acc[i][1], acc[i][2], acc[i][3]);
}

// ---------------- split-reduce + causal softmax ----------------
// grid (64 t, 16 bh), block 64 (one thread per s). Writes att transposed [bh][s][t].
__global__ void softmax_kernel()
{
    const int bh = blockIdx.y;
    const int t  = blockIdx.x;
    const int s  = threadIdx.x;

    float ssum = 0.f;
    for (int sp = 0; sp < 64; ++sp)
        ssum += g_part[((size_t)(sp*16 + bh)*64 + t)*64 + s];

    const float scale = rsqrtf(32768.0f);   // 1/sqrt(D)
    const bool valid = (s <= t);
    float logit = valid ? ssum * scale : -INFINITY;

    __shared__ float red[64];
    red[s] = logit;
    __syncthreads();
    for (int off = 32; off > 0; off >>= 1) {
        if (s < off) red[s] = fmaxf(red[s], red[s + off]);
        __syncthreads();
    }
    float mx = red[0];
    __syncthreads();
    float e = valid ? expf(logit - mx) : 0.f;
    red[s] = e;
    __syncthreads();
    for (int off = 32; off > 0; off >>= 1) {
        if (s < off) red[s] += red[s + off];
        __syncthreads();
    }
    float p = e / red[0];
    g_att[(bh*64 + s)*64 + t] = p;
}

// ---------------- y = att @ V ----------------
// grid (128 d-chunks, 16 bh), block 256; thread owns one d column, 64 t accumulators.
// V read exactly once (coalesced); att from smem broadcast (free).
__global__ void __launch_bounds__(256) av_kernel()
{
    __shared__ float4 sa[64][16];   // att[bh][s][t] as float4 over t
    const int bh = blockIdx.y;
    const int b  = bh >> 3, h = bh & 7;
    const int d  = blockIdx.x*256 + threadIdx.x;

    for (int i = threadIdx.x; i < 1024; i += 256) {
        int s = i >> 4; int tg = i & 15;
        sa[s][tg] = *(const float4*)(g_att + (bh*64 + s)*64 + tg*4);
    }
    __syncthreads();

    float acc[64];
#pragma unroll
    for (int t = 0; t < 64; ++t) acc[t] = 0.f;

#pragma unroll 2
    for (int s = 0; s < 64; ++s) {
        float vv = g_v[((size_t)((b*64 + s)*16 + h*2))*HW + d];
#pragma unroll
        for (int tg = 0; tg < 16; ++tg) {
            float4 a = sa[s][tg];
            acc[tg*4+0] = fmaf(a.x, vv, acc[tg*4+0]);
            acc[tg*4+1] = fmaf(a.y, vv, acc[tg*4+1]);
            acc[tg*4+2] = fmaf(a.z, vv, acc[tg*4+2]);
            acc[tg*4+3] = fmaf(a.w, vv, acc[tg*4+3]);
        }
    }

#pragma unroll
    for (int t = 0; t < 64; ++t)
        g_q[((size_t)((b*64 + t)*16 + h*2))*HW + d] = acc[t];  // y aliases g_q
}

// ---------------- launch ----------------
extern "C" void kernel_launch(void* const* d_in, const int* in_sizes, int n_in,
                              void* d_out, int out_size)
{
    const float* x  = (const float*)d_in[0];
    const float* wq = (const float*)d_in[1];
    const float* bq = (const float*)d_in[2];
    const float* wk = (const float*)d_in[3];
    const float* bk = (const float*)d_in[4];
    const float* wv = (const float*)d_in[5];
    const float* bv = (const float*)d_in[6];
    const float* wo = (const float*)d_in[7];
    const float* bo = (const float*)d_in[8];
    float* out = (float*)d_out;

    const int smem3 = (16*10*35 + 48*16*12 + 48) * 4;  // 59456 B
    const int smem1 = (16*10*35 + 16*16*12 + 16) * 4;  // 34752 B
    cudaFuncSetAttribute(conv3x3_kernel<3>, cudaFuncAttributeMaxDynamicSharedMemorySize, smem3);
    cudaFuncSetAttribute(conv3x3_kernel<1>, cudaFuncAttributeMaxDynamicSharedMemorySize, smem1);

    dim3 cgrid(64, 128);   // 64 spatial tiles x 128 images
    conv3x3_kernel<3><<<cgrid, 256, smem3>>>(x, wq, bq, wk, bk, wv, bv, nullptr);
    qk_kernel<<<dim3(64, 16), 256>>>();
    softmax_kernel<<<dim3(64, 16), 64>>>();
    av_kernel<<<dim3(128, 16), 256>>>();
    conv3x3_kernel<1><<<cgrid, 256, smem1>>>(nullptr, wo, bo, nullptr, nullptr,
                                             nullptr, nullptr, out);
}